// round 4
// baseline (speedup 1.0000x reference)
#include <cuda_runtime.h>
#include <cuda_bf16.h>
#include <cstdint>

#define N_SAMP 4096
#define Fh 15
#define Wd 120
#define NWIN 12
#define Sw 10
#define Pn 105
#define HPR 270
#define K1 43200
#define N1 512
#define BK 64
#define NT (K1 / BK)   // 675
#define STAGES 3

// ---------------- device-global scratch (no allocations anywhere) ----------
__device__ __nv_bfloat16 g_Ahi[(size_t)N_SAMP * K1];  // 354 MB
__device__ __nv_bfloat16 g_Alo[(size_t)N_SAMP * K1];  // 354 MB
__device__ __nv_bfloat16 g_Whi[(size_t)N1 * K1];      // 44 MB
__device__ __nv_bfloat16 g_Wlo[(size_t)N1 * K1];      // 44 MB
__device__ float g_y1[(size_t)N_SAMP * N1];           // 8 MB

// ---------------- helpers ---------------------------------------------------
__device__ __forceinline__ float ffill(float x) {
    unsigned u = __float_as_uint(x);
    return ((u & 0x7f800000u) == 0x7f800000u) ? 0.0f : x;
}
__device__ __forceinline__ uint32_t smem_u32(const void* p) {
    uint32_t a;
    asm("{ .reg .u64 t; cvta.to.shared.u64 t, %1; cvt.u32.u64 %0, t; }" : "=r"(a) : "l"(p));
    return a;
}
#define SWZ(o) ((o) ^ (((o) >> 3) & 0x70))

__device__ __forceinline__ void ldsm4(uint32_t* r, uint32_t addr) {
    asm volatile("ldmatrix.sync.aligned.m8n8.x4.shared.b16 {%0,%1,%2,%3}, [%4];"
                 : "=r"(r[0]), "=r"(r[1]), "=r"(r[2]), "=r"(r[3]) : "r"(addr));
}
__device__ __forceinline__ void hmma(float* d, const uint32_t* a, const uint32_t* b) {
    asm volatile(
        "mma.sync.aligned.m16n8k16.row.col.f32.bf16.bf16.f32 "
        "{%0,%1,%2,%3},{%4,%5,%6,%7},{%8,%9},{%0,%1,%2,%3};"
        : "+f"(d[0]), "+f"(d[1]), "+f"(d[2]), "+f"(d[3])
        : "r"(a[0]), "r"(a[1]), "r"(a[2]), "r"(a[3]), "r"(b[0]), "r"(b[1]));
}

// ============================================================================
// Kernel 1: features + BN + Conv + ReLU -> bf16 hi/lo planes
// ============================================================================
__global__ __launch_bounds__(256) void feat_kernel(
    const float* __restrict__ data,
    const float* __restrict__ bn_gamma, const float* __restrict__ bn_beta,
    const float* __restrict__ bn_mean, const float* __restrict__ bn_var,
    const float* __restrict__ conv_w, const float* __restrict__ conv_b)
{
    __shared__ float sd[Fh * Wd];
    __shared__ float sstd[Fh * NWIN];
    __shared__ float sfeat[HPR * NWIN];
    __shared__ float scw[48];
    __shared__ float scb[16];

    const int tid = threadIdx.x;
    const int n = blockIdx.x;
    const float* dptr = data + (size_t)n * (Fh * Wd);
    for (int i = tid; i < Fh * Wd; i += 256) sd[i] = dptr[i];
    if (tid < 48) scw[tid] = conv_w[tid];
    if (tid >= 64 && tid < 80) scb[tid - 64] = conv_b[tid - 64];
    const float bscale = rsqrtf(bn_var[0] + 1e-5f) * bn_gamma[0];
    const float bshift = bn_beta[0] - bn_mean[0] * bscale;
    __syncthreads();

    if (tid < Fh * NWIN) {
        const int f = tid / NWIN, w = tid % NWIN;
        float* seg = &sd[f * Wd + w * Sw];
        float mean = 0.f;
        #pragma unroll
        for (int s = 0; s < Sw; s++) mean += seg[s];
        mean *= 0.1f;
        float ret = ffill(seg[Sw - 1] / seg[0] - 1.0f);
        float dl = 0.f;
        #pragma unroll
        for (int s = 0; s < Sw; s++) dl += seg[s] * (float)(s + 1);
        dl *= (1.0f / 55.0f);
        float ss = 0.f;
        #pragma unroll
        for (int s = 0; s < Sw; s++) { float sp = seg[s] - mean; seg[s] = sp; ss += sp * sp; }
        const float sdv = sqrtf(ss * (1.0f / 9.0f));
        sstd[tid] = sdv;
        sfeat[(210 + f) * NWIN + w] = ffill(sdv) * bscale + bshift;
        sfeat[(225 + f) * NWIN + w] = ffill(mean / sdv) * bscale + bshift;
        sfeat[(240 + f) * NWIN + w] = ret * bscale + bshift;
        sfeat[(255 + f) * NWIN + w] = ffill(dl) * bscale + bshift;
    }
    __syncthreads();

    for (int idx = tid; idx < Pn * NWIN; idx += 256) {
        const int p = idx / NWIN, w = idx % NWIN;
        int i = 0, rem = p;
        while (rem >= 14 - i) { rem -= 14 - i; i++; }
        const int j = i + 1 + rem;
        const float* si = &sd[i * Wd + w * Sw];
        const float* sj = &sd[j * Wd + w * Sw];
        float dot = 0.f;
        #pragma unroll
        for (int s = 0; s < Sw; s++) dot += si[s] * sj[s];
        const float cov = dot * (1.0f / 9.0f);
        const float corr = ffill(cov / (sstd[i * NWIN + w] * sstd[j * NWIN + w]) * 0.9f);
        sfeat[p * NWIN + w]         = corr * bscale + bshift;
        sfeat[(105 + p) * NWIN + w] = ffill(cov) * bscale + bshift;
    }
    __syncthreads();

    // Conv + ReLU, split fp32 -> bf16 hi + bf16 lo planes
    __nv_bfloat16* ah = g_Ahi + (size_t)n * K1;
    __nv_bfloat16* al = g_Alo + (size_t)n * K1;
    for (int idx = tid; idx < K1; idx += 256) {
        const int o = idx / 2700;
        const int rem = idx - o * 2700;
        const int h = rem / 10;
        const int wc = rem - h * 10;
        const float* fr = &sfeat[h * NWIN + wc];
        float v = scb[o] + scw[o * 3] * fr[0] + scw[o * 3 + 1] * fr[1] + scw[o * 3 + 2] * fr[2];
        v = fmaxf(v, 0.0f);
        __nv_bfloat16 hi = __float2bfloat16(v);
        __nv_bfloat16 lo = __float2bfloat16(v - __bfloat162float(hi));
        ah[idx] = hi;
        al[idx] = lo;
    }
}

// ============================================================================
// Kernel 1b: split fc1 weights into bf16 hi/lo planes
// ============================================================================
__global__ __launch_bounds__(256) void wconv_kernel(const float* __restrict__ w) {
    const size_t i = ((size_t)blockIdx.x * 256 + threadIdx.x) * 4;
    float4 v = *(const float4*)(w + i);
    ushort4 hs, ls;
    {
        __nv_bfloat16 h = __float2bfloat16(v.x);
        hs.x = __bfloat16_as_ushort(h);
        ls.x = __bfloat16_as_ushort(__float2bfloat16(v.x - __bfloat162float(h)));
    }
    {
        __nv_bfloat16 h = __float2bfloat16(v.y);
        hs.y = __bfloat16_as_ushort(h);
        ls.y = __bfloat16_as_ushort(__float2bfloat16(v.y - __bfloat162float(h)));
    }
    {
        __nv_bfloat16 h = __float2bfloat16(v.z);
        hs.z = __bfloat16_as_ushort(h);
        ls.z = __bfloat16_as_ushort(__float2bfloat16(v.z - __bfloat162float(h)));
    }
    {
        __nv_bfloat16 h = __float2bfloat16(v.w);
        hs.w = __bfloat16_as_ushort(h);
        ls.w = __bfloat16_as_ushort(__float2bfloat16(v.w - __bfloat162float(h)));
    }
    *(ushort4*)((unsigned short*)g_Whi + i) = hs;
    *(ushort4*)((unsigned short*)g_Wlo + i) = ls;
}

// ============================================================================
// Kernel 2: fc1 via mma.sync bf16 split GEMM (sm_103-baseline tensor path)
// Y = relu((Ahi+Alo)@(Whi+Wlo)^T + b), dropping lo*lo.
// CTA 128x128, warp grid 2x4 (warp tile 64x32), BK=64, 3-stage cp.async.
// smem per stage: 4 planes x [128 rows x 128B] (SW128 swizzle) = 64KB.
// ============================================================================
__global__ __launch_bounds__(256) void fc1_mma(const float* __restrict__ bias)
{
    extern __shared__ __align__(1024) char smem[];
    const int tid = threadIdx.x;
    const int bx = blockIdx.x;   // N tile 0..3
    const int by = blockIdx.y;   // M tile 0..31
    const int warp = tid >> 5, lane = tid & 31;
    const int wm = warp >> 2;    // 0..1
    const int wn = warp & 3;     // 0..3
    const uint32_t sbase = smem_u32(smem);

    const __nv_bfloat16* gp0 = g_Ahi + (size_t)(by * 128) * K1;
    const __nv_bfloat16* gp1 = g_Alo + (size_t)(by * 128) * K1;
    const __nv_bfloat16* gp2 = g_Whi + (size_t)(bx * 128) * K1;
    const __nv_bfloat16* gp3 = g_Wlo + (size_t)(bx * 128) * K1;

    // per-thread cp.async geometry: chunk (16B) ch fixed, 4 rows per plane
    const int ch = tid & 7;
    const int rbase = tid >> 3;  // 0..31

    auto issue_stage = [&](int kt, int slot) {
        const int k0 = kt * BK;
        const uint32_t sb = sbase + (uint32_t)slot * 65536u;
        #pragma unroll
        for (int p = 0; p < 16; p++) {
            const int plane = p >> 2;
            const int row = ((p & 3) << 5) + rbase;
            const __nv_bfloat16* g =
                (plane == 0 ? gp0 : plane == 1 ? gp1 : plane == 2 ? gp2 : gp3)
                + (size_t)row * K1 + k0 + ch * 8;
            const uint32_t sa = sb + (uint32_t)plane * 16384u
                              + SWZ((uint32_t)(row * 128 + ch * 16));
            asm volatile("cp.async.cg.shared.global [%0], [%1], 16;"
                         :: "r"(sa), "l"(g));
        }
        asm volatile("cp.async.commit_group;");
    };

    issue_stage(0, 0);
    issue_stage(1, 1);

    float acc[4][4][4];
    #pragma unroll
    for (int i = 0; i < 4; i++)
        #pragma unroll
        for (int j = 0; j < 4; j++)
            #pragma unroll
            for (int q = 0; q < 4; q++) acc[i][j][q] = 0.f;

    // ldmatrix per-lane address components
    const uint32_t a_row_off = (uint32_t)((wm * 64 + (lane & 15)) * 128);
    const uint32_t a_k_off   = (uint32_t)((lane >> 4) << 4);
    const uint32_t b_row_off = (uint32_t)((wn * 32 + ((lane >> 4) << 3) + (lane & 7)) * 128);
    const uint32_t b_k_off   = (uint32_t)(((lane >> 3) & 1) << 4);

    for (int kt = 0; kt < NT; kt++) {
        asm volatile("cp.async.wait_group 1;");
        __syncthreads();
        if (kt + 2 < NT) issue_stage(kt + 2, (kt + 2) % STAGES);
        else asm volatile("cp.async.commit_group;");

        const uint32_t sb = sbase + (uint32_t)(kt % STAGES) * 65536u;
        #pragma unroll
        for (int s = 0; s < 4; s++) {
            uint32_t ahi[4][4], alo[4][4];
            #pragma unroll
            for (int mt = 0; mt < 4; mt++) {
                const uint32_t off = a_row_off + mt * 2048 + s * 32 + a_k_off;
                ldsm4(ahi[mt], sb + SWZ(off));
                ldsm4(alo[mt], sb + 16384u + SWZ(off));
            }
            uint32_t bhi[2][4], blo[2][4];
            #pragma unroll
            for (int q = 0; q < 2; q++) {
                const uint32_t off = b_row_off + q * 2048 + s * 32 + b_k_off;
                ldsm4(bhi[q], sb + 32768u + SWZ(off));
                ldsm4(blo[q], sb + 49152u + SWZ(off));
            }
            #pragma unroll
            for (int mt = 0; mt < 4; mt++)
                #pragma unroll
                for (int nt = 0; nt < 4; nt++) {
                    const uint32_t* bh = &bhi[nt >> 1][(nt & 1) << 1];
                    const uint32_t* bl = &blo[nt >> 1][(nt & 1) << 1];
                    hmma(acc[mt][nt], ahi[mt], bh);
                    hmma(acc[mt][nt], ahi[mt], bl);
                    hmma(acc[mt][nt], alo[mt], bh);
                }
        }
    }

    // epilogue: bias + relu, float2 stores
    #pragma unroll
    for (int mt = 0; mt < 4; mt++) {
        const int r0 = by * 128 + wm * 64 + mt * 16 + (lane >> 2);
        #pragma unroll
        for (int nt = 0; nt < 4; nt++) {
            const int c = bx * 128 + wn * 32 + nt * 8 + ((lane & 3) << 1);
            const float b0 = __ldg(bias + c), b1 = __ldg(bias + c + 1);
            float2 v0, v1;
            v0.x = fmaxf(acc[mt][nt][0] + b0, 0.f);
            v0.y = fmaxf(acc[mt][nt][1] + b1, 0.f);
            v1.x = fmaxf(acc[mt][nt][2] + b0, 0.f);
            v1.y = fmaxf(acc[mt][nt][3] + b1, 0.f);
            *(float2*)(g_y1 + (size_t)r0 * N1 + c) = v0;
            *(float2*)(g_y1 + (size_t)(r0 + 8) * N1 + c) = v1;
        }
    }
}

// ============================================================================
// Kernel 3: fused fc2(sigmoid) + fc3
// ============================================================================
__global__ __launch_bounds__(256) void fc23_kernel(
    const float* __restrict__ w2, const float* __restrict__ b2,
    const float* __restrict__ w3, const float* __restrict__ b3,
    float* __restrict__ out)
{
    __shared__ float As[32][32];
    __shared__ float Bs[32][128];
    __shared__ float sbuf[32][128];
    __shared__ float sw3[128];

    const int tid = threadIdx.x;
    const int mb = blockIdx.x;
    const float* Ab = g_y1 + (size_t)(mb * 32) * N1;
    if (tid < 128) sw3[tid] = w3[tid];
    const int tm = tid >> 5;
    const int tn = tid & 31;

    float acc[4][4] = {};
    for (int kt = 0; kt < 16; kt++) {
        const int k0 = kt * 32;
        {
            const int row = tid >> 3, kq = (tid & 7) << 2;
            float4 a = *(const float4*)(Ab + (size_t)row * N1 + k0 + kq);
            As[kq + 0][row] = a.x; As[kq + 1][row] = a.y;
            As[kq + 2][row] = a.z; As[kq + 3][row] = a.w;
        }
        #pragma unroll
        for (int q = 0; q < 4; q++) {
            const int v = tid + q * 256;
            const int row = v >> 3, kq = (v & 7) << 2;
            float4 b = *(const float4*)(w2 + (size_t)row * N1 + k0 + kq);
            Bs[kq + 0][row] = b.x; Bs[kq + 1][row] = b.y;
            Bs[kq + 2][row] = b.z; Bs[kq + 3][row] = b.w;
        }
        __syncthreads();
        #pragma unroll
        for (int k = 0; k < 32; k++) {
            float ra[4], rb[4];
            *(float4*)ra = *(const float4*)&As[k][tm * 4];
            *(float4*)rb = *(const float4*)&Bs[k][tn * 4];
            #pragma unroll
            for (int i = 0; i < 4; i++)
                #pragma unroll
                for (int j = 0; j < 4; j++) acc[i][j] += ra[i] * rb[j];
        }
        __syncthreads();
    }

    #pragma unroll
    for (int i = 0; i < 4; i++)
        #pragma unroll
        for (int j = 0; j < 4; j++) {
            const float v = acc[i][j] + b2[tn * 4 + j];
            sbuf[tm * 4 + i][tn * 4 + j] = 1.0f / (1.0f + expf(-v));
        }
    __syncthreads();

    #pragma unroll
    for (int r = 0; r < 4; r++) {
        const int row = tm * 4 + r;
        float s = sbuf[row][tn] * sw3[tn] + sbuf[row][tn + 32] * sw3[tn + 32]
                + sbuf[row][tn + 64] * sw3[tn + 64] + sbuf[row][tn + 96] * sw3[tn + 96];
        #pragma unroll
        for (int o = 16; o; o >>= 1) s += __shfl_down_sync(0xffffffffu, s, o);
        if (tn == 0) out[mb * 32 + row] = s + b3[0];
    }
}

// ============================================================================
extern "C" void kernel_launch(void* const* d_in, const int* in_sizes, int n_in,
                              void* d_out, int out_size) {
    const float* data   = (const float*)d_in[0];
    const float* gamma  = (const float*)d_in[1];
    const float* beta   = (const float*)d_in[2];
    const float* mean   = (const float*)d_in[3];
    const float* var    = (const float*)d_in[4];
    const float* conv_w = (const float*)d_in[5];
    const float* conv_b = (const float*)d_in[6];
    const float* fc1_w  = (const float*)d_in[7];
    const float* fc1_b  = (const float*)d_in[8];
    const float* fc2_w  = (const float*)d_in[9];
    const float* fc2_b  = (const float*)d_in[10];
    const float* fc3_w  = (const float*)d_in[11];
    const float* fc3_b  = (const float*)d_in[12];
    float* out = (float*)d_out;

    const int smem_sz = STAGES * 4 * 16384;  // 196608
    cudaFuncSetAttribute(fc1_mma, cudaFuncAttributeMaxDynamicSharedMemorySize, smem_sz);

    feat_kernel<<<N_SAMP, 256>>>(data, gamma, beta, mean, var, conv_w, conv_b);
    wconv_kernel<<<(N1 * K1) / (256 * 4), 256>>>(fc1_w);
    dim3 g1(4, 32);
    fc1_mma<<<g1, 256, smem_sz>>>(fc1_b);
    fc23_kernel<<<128, 256>>>(fc2_w, fc2_b, fc3_w, fc3_b, out);
}

// round 5
// speedup vs baseline: 1.0264x; 1.0264x over previous
#include <cuda_runtime.h>
#include <cuda_fp16.h>
#include <cstdint>

#define N_SAMP 4096
#define Fh 15
#define Wd 120
#define NWIN 12
#define Sw 10
#define Pn 105
#define HPR 270
#define K1 43200
#define N1 512
#define BK 64
#define NT (K1 / BK)   // 675
#define STAGES 3
#define WBLOCKS ((N1 * K1) / (256 * 4))  // 21600

// ---------------- device-global scratch (no allocations anywhere) ----------
// A = 64*a1 + a2 (fp16 planes); W = w1 + w2/64 (w2 stored pre-scaled by 64)
__device__ __half g_A1[(size_t)N_SAMP * K1];  // 354 MB
__device__ __half g_A2[(size_t)N_SAMP * K1];  // 354 MB
__device__ __half g_W1[(size_t)N1 * K1];      // 44 MB
__device__ __half g_W2[(size_t)N1 * K1];      // 44 MB
__device__ float g_y1[(size_t)N_SAMP * N1];   // 8 MB

// ---------------- helpers ---------------------------------------------------
__device__ __forceinline__ float ffill(float x) {
    unsigned u = __float_as_uint(x);
    return ((u & 0x7f800000u) == 0x7f800000u) ? 0.0f : x;
}
__device__ __forceinline__ uint32_t smem_u32(const void* p) {
    uint32_t a;
    asm("{ .reg .u64 t; cvta.to.shared.u64 t, %1; cvt.u32.u64 %0, t; }" : "=r"(a) : "l"(p));
    return a;
}
#define SWZ(o) ((o) ^ (((o) >> 3) & 0x70))

__device__ __forceinline__ void ldsm4(uint32_t* r, uint32_t addr) {
    asm volatile("ldmatrix.sync.aligned.m8n8.x4.shared.b16 {%0,%1,%2,%3}, [%4];"
                 : "=r"(r[0]), "=r"(r[1]), "=r"(r[2]), "=r"(r[3]) : "r"(addr));
}
// fp32-accumulator fp16 MMA (main hh plane)
__device__ __forceinline__ void hmma_f32(float* d, const uint32_t* a, const uint32_t* b) {
    asm volatile(
        "mma.sync.aligned.m16n8k16.row.col.f32.f16.f16.f32 "
        "{%0,%1,%2,%3},{%4,%5,%6,%7},{%8,%9},{%0,%1,%2,%3};"
        : "+f"(d[0]), "+f"(d[1]), "+f"(d[2]), "+f"(d[3])
        : "r"(a[0]), "r"(a[1]), "r"(a[2]), "r"(a[3]), "r"(b[0]), "r"(b[1]));
}
// fp16-accumulator fp16 MMA (cross planes; hoped double-rate)
__device__ __forceinline__ void hmma_f16(uint32_t* d, const uint32_t* a, const uint32_t* b) {
    asm volatile(
        "mma.sync.aligned.m16n8k16.row.col.f16.f16.f16.f16 "
        "{%0,%1},{%2,%3,%4,%5},{%6,%7},{%0,%1};"
        : "+r"(d[0]), "+r"(d[1])
        : "r"(a[0]), "r"(a[1]), "r"(a[2]), "r"(a[3]), "r"(b[0]), "r"(b[1]));
}

// ============================================================================
// Kernel 1 (fused): blocks [0,4096) = features+BN+conv+ReLU -> A planes
//                   blocks [4096, 4096+WBLOCKS) = fc1 weight split -> W planes
// ============================================================================
__global__ __launch_bounds__(256) void feat_kernel(
    const float* __restrict__ data,
    const float* __restrict__ bn_gamma, const float* __restrict__ bn_beta,
    const float* __restrict__ bn_mean, const float* __restrict__ bn_var,
    const float* __restrict__ conv_w, const float* __restrict__ conv_b,
    const float* __restrict__ fc1_w)
{
    const int tid = threadIdx.x;

    if (blockIdx.x >= N_SAMP) {
        // ---- weight-split role ----
        const size_t i = ((size_t)(blockIdx.x - N_SAMP) * 256 + tid) * 4;
        float4 v = *(const float4*)(fc1_w + i);
        __half w1x = __float2half_rn(v.x);
        __half w1y = __float2half_rn(v.y);
        __half w1z = __float2half_rn(v.z);
        __half w1w = __float2half_rn(v.w);
        ushort4 h1, h2;
        h1.x = __half_as_ushort(w1x);
        h1.y = __half_as_ushort(w1y);
        h1.z = __half_as_ushort(w1z);
        h1.w = __half_as_ushort(w1w);
        h2.x = __half_as_ushort(__float2half_rn((v.x - __half2float(w1x)) * 64.0f));
        h2.y = __half_as_ushort(__float2half_rn((v.y - __half2float(w1y)) * 64.0f));
        h2.z = __half_as_ushort(__float2half_rn((v.z - __half2float(w1z)) * 64.0f));
        h2.w = __half_as_ushort(__float2half_rn((v.w - __half2float(w1w)) * 64.0f));
        *(ushort4*)((unsigned short*)g_W1 + i) = h1;
        *(ushort4*)((unsigned short*)g_W2 + i) = h2;
        return;
    }

    // ---- feature role ----
    __shared__ float sd[Fh * Wd];
    __shared__ float sstd[Fh * NWIN];
    __shared__ float sfeat[HPR * NWIN];
    __shared__ float scw[48];
    __shared__ float scb[16];

    const int n = blockIdx.x;
    const float* dptr = data + (size_t)n * (Fh * Wd);
    for (int i = tid; i < Fh * Wd; i += 256) sd[i] = dptr[i];
    if (tid < 48) scw[tid] = conv_w[tid];
    if (tid >= 64 && tid < 80) scb[tid - 64] = conv_b[tid - 64];
    const float bscale = rsqrtf(bn_var[0] + 1e-5f) * bn_gamma[0];
    const float bshift = bn_beta[0] - bn_mean[0] * bscale;
    __syncthreads();

    if (tid < Fh * NWIN) {
        const int f = tid / NWIN, w = tid % NWIN;
        float* seg = &sd[f * Wd + w * Sw];
        float mean = 0.f;
        #pragma unroll
        for (int s = 0; s < Sw; s++) mean += seg[s];
        mean *= 0.1f;
        float ret = ffill(seg[Sw - 1] / seg[0] - 1.0f);
        float dl = 0.f;
        #pragma unroll
        for (int s = 0; s < Sw; s++) dl += seg[s] * (float)(s + 1);
        dl *= (1.0f / 55.0f);
        float ss = 0.f;
        #pragma unroll
        for (int s = 0; s < Sw; s++) { float sp = seg[s] - mean; seg[s] = sp; ss += sp * sp; }
        const float sdv = sqrtf(ss * (1.0f / 9.0f));
        sstd[tid] = sdv;
        sfeat[(210 + f) * NWIN + w] = ffill(sdv) * bscale + bshift;
        sfeat[(225 + f) * NWIN + w] = ffill(mean / sdv) * bscale + bshift;
        sfeat[(240 + f) * NWIN + w] = ret * bscale + bshift;
        sfeat[(255 + f) * NWIN + w] = ffill(dl) * bscale + bshift;
    }
    __syncthreads();

    for (int idx = tid; idx < Pn * NWIN; idx += 256) {
        const int p = idx / NWIN, w = idx % NWIN;
        int i = 0, rem = p;
        while (rem >= 14 - i) { rem -= 14 - i; i++; }
        const int j = i + 1 + rem;
        const float* si = &sd[i * Wd + w * Sw];
        const float* sj = &sd[j * Wd + w * Sw];
        float dot = 0.f;
        #pragma unroll
        for (int s = 0; s < Sw; s++) dot += si[s] * sj[s];
        const float cov = dot * (1.0f / 9.0f);
        const float corr = ffill(cov / (sstd[i * NWIN + w] * sstd[j * NWIN + w]) * 0.9f);
        sfeat[p * NWIN + w]         = corr * bscale + bshift;
        sfeat[(105 + p) * NWIN + w] = ffill(cov) * bscale + bshift;
    }
    __syncthreads();

    // Conv + ReLU, A = 64*a1 + a2 fp16 split
    __half* p1 = g_A1 + (size_t)n * K1;
    __half* p2 = g_A2 + (size_t)n * K1;
    for (int idx = tid; idx < K1; idx += 256) {
        const int o = idx / 2700;
        const int rem = idx - o * 2700;
        const int h = rem / 10;
        const int wc = rem - h * 10;
        const float* fr = &sfeat[h * NWIN + wc];
        float v = scb[o] + scw[o * 3] * fr[0] + scw[o * 3 + 1] * fr[1] + scw[o * 3 + 2] * fr[2];
        v = fmaxf(v, 0.0f);
        __half a1 = __float2half_rn(v * 0.015625f);
        __half a2 = __float2half_rn(v - 64.0f * __half2float(a1));
        p1[idx] = a1;
        p2[idx] = a2;
    }
}

// ============================================================================
// Kernel 2: fc1 split-fp16 GEMM
// y1 = relu( 64*(A1@W1^T)[f32acc] + (A1@W2^T + A2@W1^T)[f16acc] + b )
// CTA 128x128, warp 64x32, BK=64, 3-stage cp.async, SW128 swizzle.
// ============================================================================
__global__ __launch_bounds__(256) void fc1_mma(const float* __restrict__ bias)
{
    extern __shared__ __align__(1024) char smem[];
    const int tid = threadIdx.x;
    const int bx = blockIdx.x;   // N tile 0..3
    const int by = blockIdx.y;   // M tile 0..31
    const int warp = tid >> 5, lane = tid & 31;
    const int wm = warp >> 2;    // 0..1
    const int wn = warp & 3;     // 0..3
    const uint32_t sbase = smem_u32(smem);

    const __half* gp0 = g_A1 + (size_t)(by * 128) * K1;
    const __half* gp1 = g_A2 + (size_t)(by * 128) * K1;
    const __half* gp2 = g_W1 + (size_t)(bx * 128) * K1;
    const __half* gp3 = g_W2 + (size_t)(bx * 128) * K1;

    const int ch = tid & 7;
    const int rbase = tid >> 3;

    auto issue_stage = [&](int kt, int slot) {
        const int k0 = kt * BK;
        const uint32_t sb = sbase + (uint32_t)slot * 65536u;
        #pragma unroll
        for (int p = 0; p < 16; p++) {
            const int plane = p >> 2;
            const int row = ((p & 3) << 5) + rbase;
            const __half* g =
                (plane == 0 ? gp0 : plane == 1 ? gp1 : plane == 2 ? gp2 : gp3)
                + (size_t)row * K1 + k0 + ch * 8;
            const uint32_t sa = sb + (uint32_t)plane * 16384u
                              + SWZ((uint32_t)(row * 128 + ch * 16));
            asm volatile("cp.async.cg.shared.global [%0], [%1], 16;"
                         :: "r"(sa), "l"(g));
        }
        asm volatile("cp.async.commit_group;");
    };

    issue_stage(0, 0);
    issue_stage(1, 1);

    float acc[4][4][4];
    uint32_t hacc[4][4][2];
    #pragma unroll
    for (int i = 0; i < 4; i++)
        #pragma unroll
        for (int j = 0; j < 4; j++) {
            #pragma unroll
            for (int q = 0; q < 4; q++) acc[i][j][q] = 0.f;
            hacc[i][j][0] = 0u; hacc[i][j][1] = 0u;
        }

    const uint32_t a_row_off = (uint32_t)((wm * 64 + (lane & 15)) * 128);
    const uint32_t a_k_off   = (uint32_t)((lane >> 4) << 4);
    const uint32_t b_row_off = (uint32_t)((wn * 32 + ((lane >> 4) << 3) + (lane & 7)) * 128);
    const uint32_t b_k_off   = (uint32_t)(((lane >> 3) & 1) << 4);

    for (int kt = 0; kt < NT; kt++) {
        asm volatile("cp.async.wait_group 1;");
        __syncthreads();
        if (kt + 2 < NT) issue_stage(kt + 2, (kt + 2) % STAGES);
        else asm volatile("cp.async.commit_group;");

        const uint32_t sb = sbase + (uint32_t)(kt % STAGES) * 65536u;
        #pragma unroll
        for (int s = 0; s < 4; s++) {
            uint32_t a1f[4][4], a2f[4][4];
            #pragma unroll
            for (int mt = 0; mt < 4; mt++) {
                const uint32_t off = a_row_off + mt * 2048 + s * 32 + a_k_off;
                ldsm4(a1f[mt], sb + SWZ(off));
                ldsm4(a2f[mt], sb + 16384u + SWZ(off));
            }
            uint32_t w1f[2][4], w2f[2][4];
            #pragma unroll
            for (int q = 0; q < 2; q++) {
                const uint32_t off = b_row_off + q * 2048 + s * 32 + b_k_off;
                ldsm4(w1f[q], sb + 32768u + SWZ(off));
                ldsm4(w2f[q], sb + 49152u + SWZ(off));
            }
            #pragma unroll
            for (int mt = 0; mt < 4; mt++)
                #pragma unroll
                for (int nt = 0; nt < 4; nt++) {
                    const uint32_t* b1 = &w1f[nt >> 1][(nt & 1) << 1];
                    const uint32_t* b2 = &w2f[nt >> 1][(nt & 1) << 1];
                    hmma_f32(acc[mt][nt], a1f[mt], b1);
                    hmma_f16(hacc[mt][nt], a1f[mt], b2);
                    hmma_f16(hacc[mt][nt], a2f[mt], b1);
                }
        }
    }

    // epilogue: y = 64*hh + cross + bias, relu
    #pragma unroll
    for (int mt = 0; mt < 4; mt++) {
        const int r0 = by * 128 + wm * 64 + mt * 16 + (lane >> 2);
        #pragma unroll
        for (int nt = 0; nt < 4; nt++) {
            const int c = bx * 128 + wn * 32 + nt * 8 + ((lane & 3) << 1);
            const float b0 = __ldg(bias + c), b1 = __ldg(bias + c + 1);
            float2 c0 = __half22float2(*(half2*)&hacc[mt][nt][0]);
            float2 c1 = __half22float2(*(half2*)&hacc[mt][nt][1]);
            float2 v0, v1;
            v0.x = fmaxf(64.0f * acc[mt][nt][0] + c0.x + b0, 0.f);
            v0.y = fmaxf(64.0f * acc[mt][nt][1] + c0.y + b1, 0.f);
            v1.x = fmaxf(64.0f * acc[mt][nt][2] + c1.x + b0, 0.f);
            v1.y = fmaxf(64.0f * acc[mt][nt][3] + c1.y + b1, 0.f);
            *(float2*)(g_y1 + (size_t)r0 * N1 + c) = v0;
            *(float2*)(g_y1 + (size_t)(r0 + 8) * N1 + c) = v1;
        }
    }
}

// ============================================================================
// Kernel 3: fused fc2(sigmoid) + fc3 -- 256 blocks of 16 rows
// ============================================================================
__global__ __launch_bounds__(256) void fc23_kernel(
    const float* __restrict__ w2, const float* __restrict__ b2,
    const float* __restrict__ w3, const float* __restrict__ b3,
    float* __restrict__ out)
{
    __shared__ float As[32][16];    // [k][m]
    __shared__ float Bs[32][128];   // [k][n]
    __shared__ float sbuf[16][128];
    __shared__ float sw3[128];

    const int tid = threadIdx.x;
    const int mb = blockIdx.x;  // 0..255
    const float* Ab = g_y1 + (size_t)(mb * 16) * N1;
    if (tid < 128) sw3[tid] = w3[tid];
    const int tm = tid >> 5;  // 0..7 -> rows 2tm, 2tm+1
    const int tn = tid & 31;  // cols 4tn..

    float acc[2][4] = {};
    for (int kt = 0; kt < 16; kt++) {
        const int k0 = kt * 32;
        if (tid < 128) {
            const int row = tid >> 3, kq = (tid & 7) << 2;
            float4 a = *(const float4*)(Ab + (size_t)row * N1 + k0 + kq);
            As[kq + 0][row] = a.x; As[kq + 1][row] = a.y;
            As[kq + 2][row] = a.z; As[kq + 3][row] = a.w;
        }
        #pragma unroll
        for (int q = 0; q < 4; q++) {
            const int v = tid + q * 256;
            const int row = v >> 3, kq = (v & 7) << 2;
            float4 b = *(const float4*)(w2 + (size_t)row * N1 + k0 + kq);
            Bs[kq + 0][row] = b.x; Bs[kq + 1][row] = b.y;
            Bs[kq + 2][row] = b.z; Bs[kq + 3][row] = b.w;
        }
        __syncthreads();
        #pragma unroll
        for (int k = 0; k < 32; k++) {
            float ra[2], rb[4];
            ra[0] = As[k][tm * 2];
            ra[1] = As[k][tm * 2 + 1];
            *(float4*)rb = *(const float4*)&Bs[k][tn * 4];
            #pragma unroll
            for (int i = 0; i < 2; i++)
                #pragma unroll
                for (int j = 0; j < 4; j++) acc[i][j] += ra[i] * rb[j];
        }
        __syncthreads();
    }

    #pragma unroll
    for (int i = 0; i < 2; i++)
        #pragma unroll
        for (int j = 0; j < 4; j++) {
            const float v = acc[i][j] + b2[tn * 4 + j];
            sbuf[tm * 2 + i][tn * 4 + j] = 1.0f / (1.0f + expf(-v));
        }
    __syncthreads();

    #pragma unroll
    for (int r = 0; r < 2; r++) {
        const int row = tm * 2 + r;
        float s = sbuf[row][tn] * sw3[tn] + sbuf[row][tn + 32] * sw3[tn + 32]
                + sbuf[row][tn + 64] * sw3[tn + 64] + sbuf[row][tn + 96] * sw3[tn + 96];
        #pragma unroll
        for (int o = 16; o; o >>= 1) s += __shfl_down_sync(0xffffffffu, s, o);
        if (tn == 0) out[mb * 16 + row] = s + b3[0];
    }
}

// ============================================================================
extern "C" void kernel_launch(void* const* d_in, const int* in_sizes, int n_in,
                              void* d_out, int out_size) {
    const float* data   = (const float*)d_in[0];
    const float* gamma  = (const float*)d_in[1];
    const float* beta   = (const float*)d_in[2];
    const float* mean   = (const float*)d_in[3];
    const float* var    = (const float*)d_in[4];
    const float* conv_w = (const float*)d_in[5];
    const float* conv_b = (const float*)d_in[6];
    const float* fc1_w  = (const float*)d_in[7];
    const float* fc1_b  = (const float*)d_in[8];
    const float* fc2_w  = (const float*)d_in[9];
    const float* fc2_b  = (const float*)d_in[10];
    const float* fc3_w  = (const float*)d_in[11];
    const float* fc3_b  = (const float*)d_in[12];
    float* out = (float*)d_out;

    const int smem_sz = STAGES * 4 * 16384;  // 196608
    cudaFuncSetAttribute(fc1_mma, cudaFuncAttributeMaxDynamicSharedMemorySize, smem_sz);

    feat_kernel<<<N_SAMP + WBLOCKS, 256>>>(data, gamma, beta, mean, var,
                                           conv_w, conv_b, fc1_w);
    dim3 g1(4, 32);
    fc1_mma<<<g1, 256, smem_sz>>>(fc1_b);
    fc23_kernel<<<256, 256>>>(fc2_w, fc2_b, fc3_w, fc3_b, out);
}

// round 6
// speedup vs baseline: 1.0363x; 1.0096x over previous
#include <cuda_runtime.h>
#include <cuda_fp16.h>
#include <cstdint>

#define N_SAMP 4096
#define Fh 15
#define Wd 120
#define NWIN 12
#define Sw 10
#define Pn 105
#define HPR 270
#define K1 43200
#define N1 512
#define BK 64
#define NT (K1 / BK)   // 675
#define STAGES 3
#define WBLOCKS ((N1 * K1) / (256 * 4))  // 21600

// ---------------- device-global scratch (no allocations anywhere) ----------
// A = 64*a1 + a2 (fp16 planes); W = w1 + w2/64 (w2 stored pre-scaled by 64)
__device__ __half g_A1[(size_t)N_SAMP * K1];  // 354 MB
__device__ __half g_A2[(size_t)N_SAMP * K1];  // 354 MB
__device__ __half g_W1[(size_t)N1 * K1];      // 44 MB
__device__ __half g_W2[(size_t)N1 * K1];      // 44 MB
__device__ float g_y1[(size_t)N_SAMP * N1];   // 8 MB

// ---------------- helpers ---------------------------------------------------
__device__ __forceinline__ float ffill(float x) {
    unsigned u = __float_as_uint(x);
    return ((u & 0x7f800000u) == 0x7f800000u) ? 0.0f : x;
}
__device__ __forceinline__ uint32_t smem_u32(const void* p) {
    uint32_t a;
    asm("{ .reg .u64 t; cvta.to.shared.u64 t, %1; cvt.u32.u64 %0, t; }" : "=r"(a) : "l"(p));
    return a;
}
#define SWZ(o) ((o) ^ (((o) >> 3) & 0x70))

__device__ __forceinline__ void ldsm4(uint32_t* r, uint32_t addr) {
    asm volatile("ldmatrix.sync.aligned.m8n8.x4.shared.b16 {%0,%1,%2,%3}, [%4];"
                 : "=r"(r[0]), "=r"(r[1]), "=r"(r[2]), "=r"(r[3]) : "r"(addr));
}
__device__ __forceinline__ void hmma_f32(float* d, const uint32_t* a, const uint32_t* b) {
    asm volatile(
        "mma.sync.aligned.m16n8k16.row.col.f32.f16.f16.f32 "
        "{%0,%1,%2,%3},{%4,%5,%6,%7},{%8,%9},{%0,%1,%2,%3};"
        : "+f"(d[0]), "+f"(d[1]), "+f"(d[2]), "+f"(d[3])
        : "r"(a[0]), "r"(a[1]), "r"(a[2]), "r"(a[3]), "r"(b[0]), "r"(b[1]));
}
__device__ __forceinline__ void hmma_f16(uint32_t* d, const uint32_t* a, const uint32_t* b) {
    asm volatile(
        "mma.sync.aligned.m16n8k16.row.col.f16.f16.f16.f16 "
        "{%0,%1},{%2,%3,%4,%5},{%6,%7},{%0,%1};"
        : "+r"(d[0]), "+r"(d[1])
        : "r"(a[0]), "r"(a[1]), "r"(a[2]), "r"(a[3]), "r"(b[0]), "r"(b[1]));
}

// ============================================================================
// Kernel 1 (fused): blocks [0,4096) = features+BN+conv+ReLU -> A planes
//                   blocks [4096, 4096+WBLOCKS) = fc1 weight split -> W planes
// ============================================================================
__global__ __launch_bounds__(256) void feat_kernel(
    const float* __restrict__ data,
    const float* __restrict__ bn_gamma, const float* __restrict__ bn_beta,
    const float* __restrict__ bn_mean, const float* __restrict__ bn_var,
    const float* __restrict__ conv_w, const float* __restrict__ conv_b,
    const float* __restrict__ fc1_w)
{
    const int tid = threadIdx.x;

    if (blockIdx.x >= N_SAMP) {
        // ---- weight-split role ----
        const size_t i = ((size_t)(blockIdx.x - N_SAMP) * 256 + tid) * 4;
        float4 v = *(const float4*)(fc1_w + i);
        __half w1x = __float2half_rn(v.x);
        __half w1y = __float2half_rn(v.y);
        __half w1z = __float2half_rn(v.z);
        __half w1w = __float2half_rn(v.w);
        ushort4 h1, h2;
        h1.x = __half_as_ushort(w1x);
        h1.y = __half_as_ushort(w1y);
        h1.z = __half_as_ushort(w1z);
        h1.w = __half_as_ushort(w1w);
        h2.x = __half_as_ushort(__float2half_rn((v.x - __half2float(w1x)) * 64.0f));
        h2.y = __half_as_ushort(__float2half_rn((v.y - __half2float(w1y)) * 64.0f));
        h2.z = __half_as_ushort(__float2half_rn((v.z - __half2float(w1z)) * 64.0f));
        h2.w = __half_as_ushort(__float2half_rn((v.w - __half2float(w1w)) * 64.0f));
        *(ushort4*)((unsigned short*)g_W1 + i) = h1;
        *(ushort4*)((unsigned short*)g_W2 + i) = h2;
        return;
    }

    // ---- feature role ----
    __shared__ float sd[Fh * Wd];
    __shared__ float sstd[Fh * NWIN];
    __shared__ float sfeat[HPR * NWIN];
    __shared__ float scw[48];
    __shared__ float scb[16];

    const int n = blockIdx.x;
    const float* dptr = data + (size_t)n * (Fh * Wd);
    for (int i = tid; i < Fh * Wd; i += 256) sd[i] = dptr[i];
    if (tid < 48) scw[tid] = conv_w[tid];
    if (tid >= 64 && tid < 80) scb[tid - 64] = conv_b[tid - 64];
    const float bscale = rsqrtf(bn_var[0] + 1e-5f) * bn_gamma[0];
    const float bshift = bn_beta[0] - bn_mean[0] * bscale;
    __syncthreads();

    if (tid < Fh * NWIN) {
        const int f = tid / NWIN, w = tid % NWIN;
        float* seg = &sd[f * Wd + w * Sw];
        float mean = 0.f;
        #pragma unroll
        for (int s = 0; s < Sw; s++) mean += seg[s];
        mean *= 0.1f;
        float ret = ffill(seg[Sw - 1] / seg[0] - 1.0f);
        float dl = 0.f;
        #pragma unroll
        for (int s = 0; s < Sw; s++) dl += seg[s] * (float)(s + 1);
        dl *= (1.0f / 55.0f);
        float ss = 0.f;
        #pragma unroll
        for (int s = 0; s < Sw; s++) { float sp = seg[s] - mean; seg[s] = sp; ss += sp * sp; }
        const float sdv = sqrtf(ss * (1.0f / 9.0f));
        sstd[tid] = sdv;
        sfeat[(210 + f) * NWIN + w] = ffill(sdv) * bscale + bshift;
        sfeat[(225 + f) * NWIN + w] = ffill(mean / sdv) * bscale + bshift;
        sfeat[(240 + f) * NWIN + w] = ret * bscale + bshift;
        sfeat[(255 + f) * NWIN + w] = ffill(dl) * bscale + bshift;
    }
    __syncthreads();

    for (int idx = tid; idx < Pn * NWIN; idx += 256) {
        const int p = idx / NWIN, w = idx % NWIN;
        int i = 0, rem = p;
        while (rem >= 14 - i) { rem -= 14 - i; i++; }
        const int j = i + 1 + rem;
        const float* si = &sd[i * Wd + w * Sw];
        const float* sj = &sd[j * Wd + w * Sw];
        float dot = 0.f;
        #pragma unroll
        for (int s = 0; s < Sw; s++) dot += si[s] * sj[s];
        const float cov = dot * (1.0f / 9.0f);
        const float corr = ffill(cov / (sstd[i * NWIN + w] * sstd[j * NWIN + w]) * 0.9f);
        sfeat[p * NWIN + w]         = corr * bscale + bshift;
        sfeat[(105 + p) * NWIN + w] = ffill(cov) * bscale + bshift;
    }
    __syncthreads();

    // Conv + ReLU + fp16 split, restructured: 1350 (h, wc-pair) positions,
    // each thread reuses 4 sfeat values for all 16 output channels; half2 stores.
    __half* p1 = g_A1 + (size_t)n * K1;
    __half* p2 = g_A2 + (size_t)n * K1;
    for (int p = tid; p < 1350; p += 256) {
        const int h = p / 5;
        const int wc = (p - h * 5) * 2;
        const float* fr = &sfeat[h * NWIN + wc];
        const float f0 = fr[0], f1 = fr[1], f2 = fr[2], f3 = fr[3];
        const int base = h * 10 + wc;
        #pragma unroll
        for (int o = 0; o < 16; o++) {
            const float c0 = scw[3 * o], c1 = scw[3 * o + 1], c2 = scw[3 * o + 2];
            float v0 = fmaxf(scb[o] + c0 * f0 + c1 * f1 + c2 * f2, 0.f);
            float v1 = fmaxf(scb[o] + c0 * f1 + c1 * f2 + c2 * f3, 0.f);
            const __half a10 = __float2half_rn(v0 * 0.015625f);
            const __half a11 = __float2half_rn(v1 * 0.015625f);
            const __half a20 = __float2half_rn(v0 - 64.0f * __half2float(a10));
            const __half a21 = __float2half_rn(v1 - 64.0f * __half2float(a11));
            const int idx = o * 2700 + base;
            *(__half2*)(p1 + idx) = __halves2half2(a10, a11);
            *(__half2*)(p2 + idx) = __halves2half2(a20, a21);
        }
    }
}

// ============================================================================
// Kernel 2: fc1 split-fp16 GEMM
// y1 = relu( 64*(A1@W1^T)[f32acc] + (A1@W2^T + A2@W1^T)[f16acc] + b )
// CTA 128x128, warp 64x32, BK=64, 3-stage cp.async, SW128 swizzle.
// MMA issue reordered into 3 passes to break accumulator RAW chains.
// ============================================================================
__global__ __launch_bounds__(256) void fc1_mma(const float* __restrict__ bias)
{
    extern __shared__ __align__(1024) char smem[];
    const int tid = threadIdx.x;
    const int bx = blockIdx.x;   // N tile 0..3
    const int by = blockIdx.y;   // M tile 0..31
    const int warp = tid >> 5, lane = tid & 31;
    const int wm = warp >> 2;    // 0..1
    const int wn = warp & 3;     // 0..3
    const uint32_t sbase = smem_u32(smem);

    const __half* gp0 = g_A1 + (size_t)(by * 128) * K1;
    const __half* gp1 = g_A2 + (size_t)(by * 128) * K1;
    const __half* gp2 = g_W1 + (size_t)(bx * 128) * K1;
    const __half* gp3 = g_W2 + (size_t)(bx * 128) * K1;

    const int ch = tid & 7;
    const int rbase = tid >> 3;

    auto issue_stage = [&](int kt, int slot) {
        const int k0 = kt * BK;
        const uint32_t sb = sbase + (uint32_t)slot * 65536u;
        #pragma unroll
        for (int p = 0; p < 16; p++) {
            const int plane = p >> 2;
            const int row = ((p & 3) << 5) + rbase;
            const __half* g =
                (plane == 0 ? gp0 : plane == 1 ? gp1 : plane == 2 ? gp2 : gp3)
                + (size_t)row * K1 + k0 + ch * 8;
            const uint32_t sa = sb + (uint32_t)plane * 16384u
                              + SWZ((uint32_t)(row * 128 + ch * 16));
            asm volatile("cp.async.cg.shared.global [%0], [%1], 16;"
                         :: "r"(sa), "l"(g));
        }
        asm volatile("cp.async.commit_group;");
    };

    issue_stage(0, 0);
    issue_stage(1, 1);

    float acc[4][4][4];
    uint32_t hacc[4][4][2];
    #pragma unroll
    for (int i = 0; i < 4; i++)
        #pragma unroll
        for (int j = 0; j < 4; j++) {
            #pragma unroll
            for (int q = 0; q < 4; q++) acc[i][j][q] = 0.f;
            hacc[i][j][0] = 0u; hacc[i][j][1] = 0u;
        }

    const uint32_t a_row_off = (uint32_t)((wm * 64 + (lane & 15)) * 128);
    const uint32_t a_k_off   = (uint32_t)((lane >> 4) << 4);
    const uint32_t b_row_off = (uint32_t)((wn * 32 + ((lane >> 4) << 3) + (lane & 7)) * 128);
    const uint32_t b_k_off   = (uint32_t)(((lane >> 3) & 1) << 4);

    for (int kt = 0; kt < NT; kt++) {
        asm volatile("cp.async.wait_group 1;");
        __syncthreads();
        if (kt + 2 < NT) issue_stage(kt + 2, (kt + 2) % STAGES);
        else asm volatile("cp.async.commit_group;");

        const uint32_t sb = sbase + (uint32_t)(kt % STAGES) * 65536u;
        #pragma unroll
        for (int s = 0; s < 4; s++) {
            uint32_t a1f[4][4], a2f[4][4];
            #pragma unroll
            for (int mt = 0; mt < 4; mt++) {
                const uint32_t off = a_row_off + mt * 2048 + s * 32 + a_k_off;
                ldsm4(a1f[mt], sb + SWZ(off));
                ldsm4(a2f[mt], sb + 16384u + SWZ(off));
            }
            uint32_t w1f[2][4], w2f[2][4];
            #pragma unroll
            for (int q = 0; q < 2; q++) {
                const uint32_t off = b_row_off + q * 2048 + s * 32 + b_k_off;
                ldsm4(w1f[q], sb + 32768u + SWZ(off));
                ldsm4(w2f[q], sb + 49152u + SWZ(off));
            }
            // pass 1: main plane, f32 accumulators (16 independent)
            #pragma unroll
            for (int mt = 0; mt < 4; mt++)
                #pragma unroll
                for (int nt = 0; nt < 4; nt++)
                    hmma_f32(acc[mt][nt], a1f[mt], &w1f[nt >> 1][(nt & 1) << 1]);
            // pass 2: a1*w2 cross, f16 accumulators
            #pragma unroll
            for (int mt = 0; mt < 4; mt++)
                #pragma unroll
                for (int nt = 0; nt < 4; nt++)
                    hmma_f16(hacc[mt][nt], a1f[mt], &w2f[nt >> 1][(nt & 1) << 1]);
            // pass 3: a2*w1 cross, f16 accumulators (reuse distance 16)
            #pragma unroll
            for (int mt = 0; mt < 4; mt++)
                #pragma unroll
                for (int nt = 0; nt < 4; nt++)
                    hmma_f16(hacc[mt][nt], a2f[mt], &w1f[nt >> 1][(nt & 1) << 1]);
        }
    }

    // epilogue: y = 64*hh + cross + bias, relu
    #pragma unroll
    for (int mt = 0; mt < 4; mt++) {
        const int r0 = by * 128 + wm * 64 + mt * 16 + (lane >> 2);
        #pragma unroll
        for (int nt = 0; nt < 4; nt++) {
            const int c = bx * 128 + wn * 32 + nt * 8 + ((lane & 3) << 1);
            const float b0 = __ldg(bias + c), b1 = __ldg(bias + c + 1);
            float2 c0 = __half22float2(*(half2*)&hacc[mt][nt][0]);
            float2 c1 = __half22float2(*(half2*)&hacc[mt][nt][1]);
            float2 v0, v1;
            v0.x = fmaxf(64.0f * acc[mt][nt][0] + c0.x + b0, 0.f);
            v0.y = fmaxf(64.0f * acc[mt][nt][1] + c0.y + b1, 0.f);
            v1.x = fmaxf(64.0f * acc[mt][nt][2] + c1.x + b0, 0.f);
            v1.y = fmaxf(64.0f * acc[mt][nt][3] + c1.y + b1, 0.f);
            *(float2*)(g_y1 + (size_t)r0 * N1 + c) = v0;
            *(float2*)(g_y1 + (size_t)(r0 + 8) * N1 + c) = v1;
        }
    }
}

// ============================================================================
// Kernel 3: fused fc2(sigmoid) + fc3 -- 256 blocks of 16 rows
// ============================================================================
__global__ __launch_bounds__(256) void fc23_kernel(
    const float* __restrict__ w2, const float* __restrict__ b2,
    const float* __restrict__ w3, const float* __restrict__ b3,
    float* __restrict__ out)
{
    __shared__ float As[32][16];
    __shared__ float Bs[32][128];
    __shared__ float sbuf[16][128];
    __shared__ float sw3[128];

    const int tid = threadIdx.x;
    const int mb = blockIdx.x;
    const float* Ab = g_y1 + (size_t)(mb * 16) * N1;
    if (tid < 128) sw3[tid] = w3[tid];
    const int tm = tid >> 5;
    const int tn = tid & 31;

    float acc[2][4] = {};
    for (int kt = 0; kt < 16; kt++) {
        const int k0 = kt * 32;
        if (tid < 128) {
            const int row = tid >> 3, kq = (tid & 7) << 2;
            float4 a = *(const float4*)(Ab + (size_t)row * N1 + k0 + kq);
            As[kq + 0][row] = a.x; As[kq + 1][row] = a.y;
            As[kq + 2][row] = a.z; As[kq + 3][row] = a.w;
        }
        #pragma unroll
        for (int q = 0; q < 4; q++) {
            const int v = tid + q * 256;
            const int row = v >> 3, kq = (v & 7) << 2;
            float4 b = *(const float4*)(w2 + (size_t)row * N1 + k0 + kq);
            Bs[kq + 0][row] = b.x; Bs[kq + 1][row] = b.y;
            Bs[kq + 2][row] = b.z; Bs[kq + 3][row] = b.w;
        }
        __syncthreads();
        #pragma unroll
        for (int k = 0; k < 32; k++) {
            float ra[2], rb[4];
            ra[0] = As[k][tm * 2];
            ra[1] = As[k][tm * 2 + 1];
            *(float4*)rb = *(const float4*)&Bs[k][tn * 4];
            #pragma unroll
            for (int i = 0; i < 2; i++)
                #pragma unroll
                for (int j = 0; j < 4; j++) acc[i][j] += ra[i] * rb[j];
        }
        __syncthreads();
    }

    #pragma unroll
    for (int i = 0; i < 2; i++)
        #pragma unroll
        for (int j = 0; j < 4; j++) {
            const float v = acc[i][j] + b2[tn * 4 + j];
            sbuf[tm * 2 + i][tn * 4 + j] = 1.0f / (1.0f + expf(-v));
        }
    __syncthreads();

    #pragma unroll
    for (int r = 0; r < 2; r++) {
        const int row = tm * 2 + r;
        float s = sbuf[row][tn] * sw3[tn] + sbuf[row][tn + 32] * sw3[tn + 32]
                + sbuf[row][tn + 64] * sw3[tn + 64] + sbuf[row][tn + 96] * sw3[tn + 96];
        #pragma unroll
        for (int o = 16; o; o >>= 1) s += __shfl_down_sync(0xffffffffu, s, o);
        if (tn == 0) out[mb * 16 + row] = s + b3[0];
    }
}

// ============================================================================
extern "C" void kernel_launch(void* const* d_in, const int* in_sizes, int n_in,
                              void* d_out, int out_size) {
    const float* data   = (const float*)d_in[0];
    const float* gamma  = (const float*)d_in[1];
    const float* beta   = (const float*)d_in[2];
    const float* mean   = (const float*)d_in[3];
    const float* var    = (const float*)d_in[4];
    const float* conv_w = (const float*)d_in[5];
    const float* conv_b = (const float*)d_in[6];
    const float* fc1_w  = (const float*)d_in[7];
    const float* fc1_b  = (const float*)d_in[8];
    const float* fc2_w  = (const float*)d_in[9];
    const float* fc2_b  = (const float*)d_in[10];
    const float* fc3_w  = (const float*)d_in[11];
    const float* fc3_b  = (const float*)d_in[12];
    float* out = (float*)d_out;

    const int smem_sz = STAGES * 4 * 16384;  // 196608
    cudaFuncSetAttribute(fc1_mma, cudaFuncAttributeMaxDynamicSharedMemorySize, smem_sz);

    feat_kernel<<<N_SAMP + WBLOCKS, 256>>>(data, gamma, beta, mean, var,
                                           conv_w, conv_b, fc1_w);
    dim3 g1(4, 32);
    fc1_mma<<<g1, 256, smem_sz>>>(fc1_b);
    fc23_kernel<<<256, 256>>>(fc2_w, fc2_b, fc3_w, fc3_b, out);
}

// round 7
// speedup vs baseline: 1.0605x; 1.0234x over previous
#include <cuda_runtime.h>
#include <cuda_fp16.h>
#include <cstdint>

#define N_SAMP 4096
#define Fh 15
#define Wd 120
#define NWIN 12
#define Sw 10
#define Pn 105
#define HPR 270
#define K1 43200
#define N1 512
#define BK 64
#define NT (K1 / BK)   // 675
#define STAGES 3
#define WB2 2048       // weight-split blocks (grid-stride)

// ---------------- device-global scratch (no allocations anywhere) ----------
// A = 64*a1 + a2 (fp16 planes); W = w1 + w2/64 (w2 stored pre-scaled by 64)
__device__ __half g_A1[(size_t)N_SAMP * K1];  // 354 MB
__device__ __half g_A2[(size_t)N_SAMP * K1];  // 354 MB
__device__ __half g_W1[(size_t)N1 * K1];      // 44 MB
__device__ __half g_W2[(size_t)N1 * K1];      // 44 MB
__device__ float g_y1[(size_t)N_SAMP * N1];   // 8 MB

// ---------------- helpers ---------------------------------------------------
__device__ __forceinline__ float ffill(float x) {
    unsigned u = __float_as_uint(x);
    return ((u & 0x7f800000u) == 0x7f800000u) ? 0.0f : x;
}
__device__ __forceinline__ uint32_t smem_u32(const void* p) {
    uint32_t a;
    asm("{ .reg .u64 t; cvta.to.shared.u64 t, %1; cvt.u32.u64 %0, t; }" : "=r"(a) : "l"(p));
    return a;
}
#define SWZ(o) ((o) ^ (((o) >> 3) & 0x70))

__device__ __forceinline__ void ldsm4(uint32_t* r, uint32_t addr) {
    asm volatile("ldmatrix.sync.aligned.m8n8.x4.shared.b16 {%0,%1,%2,%3}, [%4];"
                 : "=r"(r[0]), "=r"(r[1]), "=r"(r[2]), "=r"(r[3]) : "r"(addr));
}
__device__ __forceinline__ void hmma_f32(float* d, const uint32_t* a, const uint32_t* b) {
    asm volatile(
        "mma.sync.aligned.m16n8k16.row.col.f32.f16.f16.f32 "
        "{%0,%1,%2,%3},{%4,%5,%6,%7},{%8,%9},{%0,%1,%2,%3};"
        : "+f"(d[0]), "+f"(d[1]), "+f"(d[2]), "+f"(d[3])
        : "r"(a[0]), "r"(a[1]), "r"(a[2]), "r"(a[3]), "r"(b[0]), "r"(b[1]));
}
__device__ __forceinline__ void hmma_f16(uint32_t* d, const uint32_t* a, const uint32_t* b) {
    asm volatile(
        "mma.sync.aligned.m16n8k16.row.col.f16.f16.f16.f16 "
        "{%0,%1},{%2,%3,%4,%5},{%6,%7},{%0,%1};"
        : "+r"(d[0]), "+r"(d[1])
        : "r"(a[0]), "r"(a[1]), "r"(a[2]), "r"(a[3]), "r"(b[0]), "r"(b[1]));
}

// ============================================================================
// Kernel 1 (fused): blocks [0,4096) = features+BN+conv+ReLU -> A planes
//                   blocks [4096, 4096+WB2) = fc1 weight split (grid-stride)
// ============================================================================
__global__ __launch_bounds__(256) void feat_kernel(
    const float* __restrict__ data,
    const float* __restrict__ bn_gamma, const float* __restrict__ bn_beta,
    const float* __restrict__ bn_mean, const float* __restrict__ bn_var,
    const float* __restrict__ conv_w, const float* __restrict__ conv_b,
    const float* __restrict__ fc1_w)
{
    const int tid = threadIdx.x;

    if (blockIdx.x >= N_SAMP) {
        // ---- weight-split role: grid-stride over 5.5M float4s ----
        const size_t stride = (size_t)WB2 * 256;
        const size_t total = (size_t)N1 * K1 / 4;
        for (size_t t = (size_t)(blockIdx.x - N_SAMP) * 256 + tid; t < total; t += stride) {
            const size_t i = t * 4;
            float4 v = *(const float4*)(fc1_w + i);
            __half w1x = __float2half_rn(v.x);
            __half w1y = __float2half_rn(v.y);
            __half w1z = __float2half_rn(v.z);
            __half w1w = __float2half_rn(v.w);
            ushort4 h1, h2;
            h1.x = __half_as_ushort(w1x);
            h1.y = __half_as_ushort(w1y);
            h1.z = __half_as_ushort(w1z);
            h1.w = __half_as_ushort(w1w);
            h2.x = __half_as_ushort(__float2half_rn((v.x - __half2float(w1x)) * 64.0f));
            h2.y = __half_as_ushort(__float2half_rn((v.y - __half2float(w1y)) * 64.0f));
            h2.z = __half_as_ushort(__float2half_rn((v.z - __half2float(w1z)) * 64.0f));
            h2.w = __half_as_ushort(__float2half_rn((v.w - __half2float(w1w)) * 64.0f));
            *(ushort4*)((unsigned short*)g_W1 + i) = h1;
            *(ushort4*)((unsigned short*)g_W2 + i) = h2;
        }
        return;
    }

    // ---- feature role ----
    __shared__ float sd[Fh * Wd];
    __shared__ float sstd[Fh * NWIN];
    __shared__ float sfeat[HPR * NWIN];
    __shared__ float scw[48];
    __shared__ float scb[16];

    const int n = blockIdx.x;
    const float* dptr = data + (size_t)n * (Fh * Wd);
    for (int i = tid; i < Fh * Wd; i += 256) sd[i] = dptr[i];
    if (tid < 48) scw[tid] = conv_w[tid];
    if (tid >= 64 && tid < 80) scb[tid - 64] = conv_b[tid - 64];
    const float bscale = rsqrtf(bn_var[0] + 1e-5f) * bn_gamma[0];
    const float bshift = bn_beta[0] - bn_mean[0] * bscale;
    __syncthreads();

    if (tid < Fh * NWIN) {
        const int f = tid / NWIN, w = tid % NWIN;
        float* seg = &sd[f * Wd + w * Sw];
        float mean = 0.f;
        #pragma unroll
        for (int s = 0; s < Sw; s++) mean += seg[s];
        mean *= 0.1f;
        float ret = ffill(seg[Sw - 1] / seg[0] - 1.0f);
        float dl = 0.f;
        #pragma unroll
        for (int s = 0; s < Sw; s++) dl += seg[s] * (float)(s + 1);
        dl *= (1.0f / 55.0f);
        float ss = 0.f;
        #pragma unroll
        for (int s = 0; s < Sw; s++) { float sp = seg[s] - mean; seg[s] = sp; ss += sp * sp; }
        const float sdv = sqrtf(ss * (1.0f / 9.0f));
        sstd[tid] = sdv;
        sfeat[(210 + f) * NWIN + w] = ffill(sdv) * bscale + bshift;
        sfeat[(225 + f) * NWIN + w] = ffill(mean / sdv) * bscale + bshift;
        sfeat[(240 + f) * NWIN + w] = ret * bscale + bshift;
        sfeat[(255 + f) * NWIN + w] = ffill(dl) * bscale + bshift;
    }
    __syncthreads();

    for (int idx = tid; idx < Pn * NWIN; idx += 256) {
        const int p = idx / NWIN, w = idx % NWIN;
        int i = 0, rem = p;
        while (rem >= 14 - i) { rem -= 14 - i; i++; }
        const int j = i + 1 + rem;
        const float* si = &sd[i * Wd + w * Sw];
        const float* sj = &sd[j * Wd + w * Sw];
        float dot = 0.f;
        #pragma unroll
        for (int s = 0; s < Sw; s++) dot += si[s] * sj[s];
        const float cov = dot * (1.0f / 9.0f);
        const float corr = ffill(cov / (sstd[i * NWIN + w] * sstd[j * NWIN + w]) * 0.9f);
        sfeat[p * NWIN + w]         = corr * bscale + bshift;
        sfeat[(105 + p) * NWIN + w] = ffill(cov) * bscale + bshift;
    }
    __syncthreads();

    // Conv + ReLU + fp16 split; moderate unroll to keep regs/occupancy healthy
    __half* p1 = g_A1 + (size_t)n * K1;
    __half* p2 = g_A2 + (size_t)n * K1;
    for (int p = tid; p < 1350; p += 256) {
        const int h = p / 5;
        const int wc = (p - h * 5) * 2;
        const float* fr = &sfeat[h * NWIN + wc];
        const float f0 = fr[0], f1 = fr[1], f2 = fr[2], f3 = fr[3];
        const int base = h * 10 + wc;
        #pragma unroll 4
        for (int o = 0; o < 16; o++) {
            const float c0 = scw[3 * o], c1 = scw[3 * o + 1], c2 = scw[3 * o + 2];
            float v0 = fmaxf(scb[o] + c0 * f0 + c1 * f1 + c2 * f2, 0.f);
            float v1 = fmaxf(scb[o] + c0 * f1 + c1 * f2 + c2 * f3, 0.f);
            const __half a10 = __float2half_rn(v0 * 0.015625f);
            const __half a11 = __float2half_rn(v1 * 0.015625f);
            const __half a20 = __float2half_rn(v0 - 64.0f * __half2float(a10));
            const __half a21 = __float2half_rn(v1 - 64.0f * __half2float(a11));
            const int idx = o * 2700 + base;
            *(__half2*)(p1 + idx) = __halves2half2(a10, a11);
            *(__half2*)(p2 + idx) = __halves2half2(a20, a21);
        }
    }
}

// ============================================================================
// Kernel 2: fc1 split-fp16 GEMM, 512 threads, warp grid 4x4 (warp tile 32x32)
// y1 = relu( 64*(A1@W1^T)[f32acc] + (A1@W2^T + A2@W1^T)[f16acc] + b )
// CTA 128x128, BK=64, 3-stage cp.async, SW128 swizzle.
// ============================================================================
__global__ __launch_bounds__(512) void fc1_mma(const float* __restrict__ bias)
{
    extern __shared__ __align__(1024) char smem[];
    const int tid = threadIdx.x;
    const int bx = blockIdx.x;   // N tile 0..3
    const int by = blockIdx.y;   // M tile 0..31
    const int warp = tid >> 5, lane = tid & 31;
    const int wm = warp >> 2;    // 0..3
    const int wn = warp & 3;     // 0..3
    const uint32_t sbase = smem_u32(smem);

    const __half* gp0 = g_A1 + (size_t)(by * 128) * K1;
    const __half* gp1 = g_A2 + (size_t)(by * 128) * K1;
    const __half* gp2 = g_W1 + (size_t)(bx * 128) * K1;
    const __half* gp3 = g_W2 + (size_t)(bx * 128) * K1;

    auto issue_stage = [&](int kt, int slot) {
        const int k0 = kt * BK;
        const uint32_t sb = sbase + (uint32_t)slot * 65536u;
        #pragma unroll
        for (int p = 0; p < 8; p++) {
            const int plane = p >> 1;
            const int v = tid + ((p & 1) << 9);
            const int row = v >> 3;      // 0..127
            const int c = v & 7;         // 16B chunk
            const __half* g =
                (plane == 0 ? gp0 : plane == 1 ? gp1 : plane == 2 ? gp2 : gp3)
                + (size_t)row * K1 + k0 + c * 8;
            const uint32_t sa = sb + (uint32_t)plane * 16384u
                              + SWZ((uint32_t)(row * 128 + c * 16));
            asm volatile("cp.async.cg.shared.global [%0], [%1], 16;"
                         :: "r"(sa), "l"(g));
        }
        asm volatile("cp.async.commit_group;");
    };

    issue_stage(0, 0);
    issue_stage(1, 1);

    float acc[2][4][4];
    uint32_t hacc[2][4][2];
    #pragma unroll
    for (int i = 0; i < 2; i++)
        #pragma unroll
        for (int j = 0; j < 4; j++) {
            #pragma unroll
            for (int q = 0; q < 4; q++) acc[i][j][q] = 0.f;
            hacc[i][j][0] = 0u; hacc[i][j][1] = 0u;
        }

    const uint32_t a_row_off = (uint32_t)((wm * 32 + (lane & 15)) * 128);
    const uint32_t a_k_off   = (uint32_t)((lane >> 4) << 4);
    const uint32_t b_row_off = (uint32_t)((wn * 32 + ((lane >> 4) << 3) + (lane & 7)) * 128);
    const uint32_t b_k_off   = (uint32_t)(((lane >> 3) & 1) << 4);

    for (int kt = 0; kt < NT; kt++) {
        asm volatile("cp.async.wait_group 1;");
        __syncthreads();
        if (kt + 2 < NT) issue_stage(kt + 2, (kt + 2) % STAGES);
        else asm volatile("cp.async.commit_group;");

        const uint32_t sb = sbase + (uint32_t)(kt % STAGES) * 65536u;
        #pragma unroll
        for (int s = 0; s < 4; s++) {
            uint32_t a1f[2][4], a2f[2][4];
            #pragma unroll
            for (int mt = 0; mt < 2; mt++) {
                const uint32_t off = a_row_off + mt * 2048 + s * 32 + a_k_off;
                ldsm4(a1f[mt], sb + SWZ(off));
                ldsm4(a2f[mt], sb + 16384u + SWZ(off));
            }
            uint32_t w1f[2][4], w2f[2][4];
            #pragma unroll
            for (int q = 0; q < 2; q++) {
                const uint32_t off = b_row_off + q * 2048 + s * 32 + b_k_off;
                ldsm4(w1f[q], sb + 32768u + SWZ(off));
                ldsm4(w2f[q], sb + 49152u + SWZ(off));
            }
            #pragma unroll
            for (int mt = 0; mt < 2; mt++)
                #pragma unroll
                for (int nt = 0; nt < 4; nt++)
                    hmma_f32(acc[mt][nt], a1f[mt], &w1f[nt >> 1][(nt & 1) << 1]);
            #pragma unroll
            for (int mt = 0; mt < 2; mt++)
                #pragma unroll
                for (int nt = 0; nt < 4; nt++)
                    hmma_f16(hacc[mt][nt], a1f[mt], &w2f[nt >> 1][(nt & 1) << 1]);
            #pragma unroll
            for (int mt = 0; mt < 2; mt++)
                #pragma unroll
                for (int nt = 0; nt < 4; nt++)
                    hmma_f16(hacc[mt][nt], a2f[mt], &w1f[nt >> 1][(nt & 1) << 1]);
        }
    }

    // epilogue: y = 64*hh + cross + bias, relu
    #pragma unroll
    for (int mt = 0; mt < 2; mt++) {
        const int r0 = by * 128 + wm * 32 + mt * 16 + (lane >> 2);
        #pragma unroll
        for (int nt = 0; nt < 4; nt++) {
            const int c = bx * 128 + wn * 32 + nt * 8 + ((lane & 3) << 1);
            const float b0 = __ldg(bias + c), b1 = __ldg(bias + c + 1);
            float2 c0 = __half22float2(*(half2*)&hacc[mt][nt][0]);
            float2 c1 = __half22float2(*(half2*)&hacc[mt][nt][1]);
            float2 v0, v1;
            v0.x = fmaxf(64.0f * acc[mt][nt][0] + c0.x + b0, 0.f);
            v0.y = fmaxf(64.0f * acc[mt][nt][1] + c0.y + b1, 0.f);
            v1.x = fmaxf(64.0f * acc[mt][nt][2] + c1.x + b0, 0.f);
            v1.y = fmaxf(64.0f * acc[mt][nt][3] + c1.y + b1, 0.f);
            *(float2*)(g_y1 + (size_t)r0 * N1 + c) = v0;
            *(float2*)(g_y1 + (size_t)(r0 + 8) * N1 + c) = v1;
        }
    }
}

// ============================================================================
// Kernel 3: fused fc2(sigmoid) + fc3 -- 256 blocks of 16 rows
// ============================================================================
__global__ __launch_bounds__(256) void fc23_kernel(
    const float* __restrict__ w2, const float* __restrict__ b2,
    const float* __restrict__ w3, const float* __restrict__ b3,
    float* __restrict__ out)
{
    __shared__ float As[32][16];
    __shared__ float Bs[32][128];
    __shared__ float sbuf[16][128];
    __shared__ float sw3[128];

    const int tid = threadIdx.x;
    const int mb = blockIdx.x;
    const float* Ab = g_y1 + (size_t)(mb * 16) * N1;
    if (tid < 128) sw3[tid] = w3[tid];
    const int tm = tid >> 5;
    const int tn = tid & 31;

    float acc[2][4] = {};
    for (int kt = 0; kt < 16; kt++) {
        const int k0 = kt * 32;
        if (tid < 128) {
            const int row = tid >> 3, kq = (tid & 7) << 2;
            float4 a = *(const float4*)(Ab + (size_t)row * N1 + k0 + kq);
            As[kq + 0][row] = a.x; As[kq + 1][row] = a.y;
            As[kq + 2][row] = a.z; As[kq + 3][row] = a.w;
        }
        #pragma unroll
        for (int q = 0; q < 4; q++) {
            const int v = tid + q * 256;
            const int row = v >> 3, kq = (v & 7) << 2;
            float4 b = *(const float4*)(w2 + (size_t)row * N1 + k0 + kq);
            Bs[kq + 0][row] = b.x; Bs[kq + 1][row] = b.y;
            Bs[kq + 2][row] = b.z; Bs[kq + 3][row] = b.w;
        }
        __syncthreads();
        #pragma unroll
        for (int k = 0; k < 32; k++) {
            float ra[2], rb[4];
            ra[0] = As[k][tm * 2];
            ra[1] = As[k][tm * 2 + 1];
            *(float4*)rb = *(const float4*)&Bs[k][tn * 4];
            #pragma unroll
            for (int i = 0; i < 2; i++)
                #pragma unroll
                for (int j = 0; j < 4; j++) acc[i][j] += ra[i] * rb[j];
        }
        __syncthreads();
    }

    #pragma unroll
    for (int i = 0; i < 2; i++)
        #pragma unroll
        for (int j = 0; j < 4; j++) {
            const float v = acc[i][j] + b2[tn * 4 + j];
            sbuf[tm * 2 + i][tn * 4 + j] = 1.0f / (1.0f + expf(-v));
        }
    __syncthreads();

    #pragma unroll
    for (int r = 0; r < 2; r++) {
        const int row = tm * 2 + r;
        float s = sbuf[row][tn] * sw3[tn] + sbuf[row][tn + 32] * sw3[tn + 32]
                + sbuf[row][tn + 64] * sw3[tn + 64] + sbuf[row][tn + 96] * sw3[tn + 96];
        #pragma unroll
        for (int o = 16; o; o >>= 1) s += __shfl_down_sync(0xffffffffu, s, o);
        if (tn == 0) out[mb * 16 + row] = s + b3[0];
    }
}

// ============================================================================
extern "C" void kernel_launch(void* const* d_in, const int* in_sizes, int n_in,
                              void* d_out, int out_size) {
    const float* data   = (const float*)d_in[0];
    const float* gamma  = (const float*)d_in[1];
    const float* beta   = (const float*)d_in[2];
    const float* mean   = (const float*)d_in[3];
    const float* var    = (const float*)d_in[4];
    const float* conv_w = (const float*)d_in[5];
    const float* conv_b = (const float*)d_in[6];
    const float* fc1_w  = (const float*)d_in[7];
    const float* fc1_b  = (const float*)d_in[8];
    const float* fc2_w  = (const float*)d_in[9];
    const float* fc2_b  = (const float*)d_in[10];
    const float* fc3_w  = (const float*)d_in[11];
    const float* fc3_b  = (const float*)d_in[12];
    float* out = (float*)d_out;

    const int smem_sz = STAGES * 4 * 16384;  // 196608
    cudaFuncSetAttribute(fc1_mma, cudaFuncAttributeMaxDynamicSharedMemorySize, smem_sz);

    feat_kernel<<<N_SAMP + WB2, 256>>>(data, gamma, beta, mean, var,
                                       conv_w, conv_b, fc1_w);
    dim3 g1(4, 32);
    fc1_mma<<<g1, 512, smem_sz>>>(fc1_b);
    fc23_kernel<<<256, 256>>>(fc2_w, fc2_b, fc3_w, fc3_b, out);
}